// round 13
// baseline (speedup 1.0000x reference)
#include <cuda_runtime.h>

#define D      64
#define NSEG   8192
#define OUT    128
#define NBLK   592   // 148 SMs x 4 resident blocks (64-reg cap)

__device__ int g_counter[2];      // dynamic segment queues, one per type
__device__ int g_order[2 * NSEG]; // size-ordered work lists (big first)

__device__ __forceinline__ void fmax4(float4& a, const float4 b) {
    a.x = fmaxf(a.x, b.x); a.y = fmaxf(a.y, b.y);
    a.z = fmaxf(a.z, b.z); a.w = fmaxf(a.w, b.w);
}

// ---------------------------------------------------------------------------
// Init: zero output (== relu floor) and both work-queue counters.
// ---------------------------------------------------------------------------
__global__ void init_kernel(float* __restrict__ out)
{
    out[threadIdx.x] = 0.0f;
    if (threadIdx.x < 2) g_counter[threadIdx.x] = 0;
}

// ---------------------------------------------------------------------------
// Order kernel: bucket segments by size into g_order, biggest bucket first.
// The R12 null result killed the sync-overhead theory; the remaining tail
// suspect is a large (up to ~2200-row) segment popped LAST and streamed by
// one block alone (~50 GB/s) while the chip idles. Big-first scheduling
// bounds the tail by a <256-row segment. Intra-bucket order is atomic-
// nondeterministic but the final output is a pure max -> order-invariant.
// ---------------------------------------------------------------------------
__global__ void order_kernel(const int* __restrict__ ptr_a,
                             const int* __restrict__ ptr_b)
{
    const int* ptr = blockIdx.x ? ptr_b : ptr_a;
    int* ord = g_order + blockIdx.x * NSEG;

    __shared__ int base[4];
    if (threadIdx.x < 4) base[threadIdx.x] = 0;
    __syncthreads();

    // pass 1: bucket counts
    for (int g = threadIdx.x; g < NSEG; g += blockDim.x) {
        int sz = ptr[g + 1] - ptr[g];
        int b  = (sz >= 1024) ? 0 : (sz >= 512) ? 1 : (sz >= 256) ? 2 : 3;
        atomicAdd(&base[b], 1);
    }
    __syncthreads();
    if (threadIdx.x == 0) {
        int c0 = base[0], c1 = base[1], c2 = base[2];
        base[0] = 0;
        base[1] = c0;
        base[2] = c0 + c1;
        base[3] = c0 + c1 + c2;
    }
    __syncthreads();

    // pass 2: scatter ids, big buckets first
    for (int g = threadIdx.x; g < NSEG; g += blockDim.x) {
        int sz  = ptr[g + 1] - ptr[g];
        int b   = (sz >= 1024) ? 0 : (sz >= 512) ? 1 : (sz >= 256) ? 2 : 3;
        int pos = atomicAdd(&base[b], 1);
        ord[pos] = g;
    }
}

// ---------------------------------------------------------------------------
// Persistent fused kernel — R11 WIN structure verbatim (164 us, DRAM 78.7%),
// with one change: the queue index is redirected through g_order so large
// segments are processed first.
// relu(max)==max(relu); int-bit atomicMax exact for non-negative floats.
// ptr arrays are int32 (JAX x64 disabled downcasts the int64 ptr).
// ---------------------------------------------------------------------------
__global__ void __launch_bounds__(256, 4)
seg_max_linear_kernel(const float* __restrict__ x_a,
                      const float* __restrict__ x_b,
                      const float* __restrict__ W_a,
                      const float* __restrict__ W_b,
                      const float* __restrict__ b_a,
                      const float* __restrict__ b_b,
                      const int* __restrict__ ptr_a,
                      const int* __restrict__ ptr_b,
                      float* __restrict__ out)
{
    const int ctype = blockIdx.x & 1;

    const float* x    = ctype ? x_b   : x_a;
    const int*   ptr  = ctype ? ptr_b : ptr_a;
    const float* W    = ctype ? W_b   : W_a;
    const float* bias = ctype ? b_b   : b_a;

    const int tid = threadIdx.x;               // 256
    const int c4  = tid & 15;                  // float4 column 0..15
    const int rg  = tid >> 4;                  // row group 0..15
    const int o   = tid >> 1;                  // epilogue output channel
    const int h   = tid & 1;                   // epilogue K-half

    __shared__ float4 sw[256][9];              // padded W, conflict-free
    __shared__ float4 sm[16][16];              // reduce scratch
    __shared__ float4 segv[D / 4];             // this segment's max vector
    __shared__ int    swork;

    // W -> shared once: coalesced LDG, scattered conflict-free STS.
    {
        const float4* __restrict__ W4g = reinterpret_cast<const float4*>(W);
        #pragma unroll
        for (int i = 0; i < 8; i++) {
            int f = tid + i * 256;             // float4 linear index into W
            float4 v = W4g[f];
            int row = f >> 4;                  // output row 0..127
            int kk  = f & 15;                  // float4 within row
            sw[(row << 1) | (kk >> 3)][kk & 7] = v;
        }
    }
    const float bo = bias[o];

    const float4* __restrict__ xv = reinterpret_cast<const float4*>(x);
    const float NEG = -3.402823466e38f;

    float lmax = 0.0f;                         // relu floor, running block max

    while (true) {
        if (tid == 0) swork = atomicAdd(&g_counter[ctype], 1);
        __syncthreads();                       // also covers sw visibility
        const int idx = swork;
        if (idx >= NSEG) break;
        const int g = g_order[ctype * NSEG + idx];   // big segments first

        const int gs = ptr[g];
        const int ge = ptr[g + 1];

        float4 m0 = make_float4(NEG, NEG, NEG, NEG);
        float4 m1 = m0, m2 = m0, m3 = m0;

        long long row = (long long)gs + rg;
        for (; row + 48 < ge; row += 64) {
            const float4* p = xv + row * (D / 4) + c4;
            float4 v0 = __ldcs(p);
            float4 v1 = __ldcs(p + 16 * (D / 4));
            float4 v2 = __ldcs(p + 32 * (D / 4));
            float4 v3 = __ldcs(p + 48 * (D / 4));
            fmax4(m0, v0); fmax4(m1, v1); fmax4(m2, v2); fmax4(m3, v3);
        }
        for (; row < ge; row += 16) {
            float4 v0 = __ldcs(xv + row * (D / 4) + c4);
            fmax4(m0, v0);
        }
        fmax4(m0, m1); fmax4(m2, m3); fmax4(m0, m2);

        sm[rg][c4] = m0;
        __syncthreads();

        if (tid < 16) {
            float4 m = sm[0][tid];
            #pragma unroll
            for (int j = 1; j < 16; j++)
                fmax4(m, sm[j][tid]);
            segv[tid] = m;
        }
        __syncthreads();

        // Epilogue: split-K half-dot from smem W (no register W copy).
        float a0 = 0.f, a1 = 0.f, a2 = 0.f, a3 = 0.f;
        #pragma unroll
        for (int k = 0; k < 8; k++) {
            float4 ww = sw[tid][k];            // W[o, h*32+4k .. +4)
            float4 u  = segv[h * 8 + k];
            a0 = fmaf(ww.x, u.x, a0);
            a1 = fmaf(ww.y, u.y, a1);
            a2 = fmaf(ww.z, u.z, a2);
            a3 = fmaf(ww.w, u.w, a3);
        }
        float hd    = (a0 + a1) + (a2 + a3);
        float other = __shfl_xor_sync(0xffffffffu, hd, 1);
        lmax = fmaxf(lmax, hd + other + bo);
        // next iteration's top-of-loop __syncthreads orders segv reuse
    }

    if (h == 0)
        atomicMax(reinterpret_cast<int*>(out) + o, __float_as_int(lmax));
}

// ---------------------------------------------------------------------------
extern "C" void kernel_launch(void* const* d_in, const int* in_sizes, int n_in,
                              void* d_out, int out_size)
{
    const float* x_a   = (const float*)d_in[0];
    const float* x_b   = (const float*)d_in[1];
    const float* W_a   = (const float*)d_in[2];
    const float* W_b   = (const float*)d_in[3];
    const float* b_a   = (const float*)d_in[4];
    const float* b_b   = (const float*)d_in[5];
    const int*   ptr_a = (const int*)d_in[6];
    const int*   ptr_b = (const int*)d_in[7];
    float* out = (float*)d_out;

    init_kernel<<<1, OUT>>>(out);
    order_kernel<<<2, 1024>>>(ptr_a, ptr_b);
    seg_max_linear_kernel<<<NBLK, 256>>>(x_a, x_b, W_a, W_b,
                                         b_a, b_b, ptr_a, ptr_b, out);
}

// round 15
// speedup vs baseline: 1.0247x; 1.0247x over previous
#include <cuda_runtime.h>

#define D      64
#define NSEG   8192
#define OUT    128
#define NBLK   592   // 148 SMs x 4 resident blocks (64-reg cap)
#define BIG    1024  // rows; segments at least this long are scheduled first

__device__ int g_counter[2];      // dynamic segment queues, one per type
__device__ int g_order[2 * NSEG]; // stable big-first work lists

__device__ __forceinline__ void fmax4(float4& a, const float4 b) {
    a.x = fmaxf(a.x, b.x); a.y = fmaxf(a.y, b.y);
    a.z = fmaxf(a.z, b.z); a.w = fmaxf(a.w, b.w);
}

// ---------------------------------------------------------------------------
// Order+init kernel (2 blocks, one per type). Stable partition of segment ids:
// big (>=BIG rows) first in ascending id order, rest after, also ascending.
// Built with a block-wide inclusive scan (deterministic; the R13 lesson was
// that atomicAdd scatter randomized intra-bucket order and cost ~11us of
// locality, confounding the tail test). Block 0 also zeroes out/counters.
// ---------------------------------------------------------------------------
__global__ void order_init_kernel(const int* __restrict__ ptr_a,
                                  const int* __restrict__ ptr_b,
                                  float* __restrict__ out)
{
    const int* ptr = blockIdx.x ? ptr_b : ptr_a;
    int* ord = g_order + blockIdx.x * NSEG;
    const int t = threadIdx.x;                 // 1024 threads, 8 ids each

    if (blockIdx.x == 0) {
        if (t < OUT) out[t] = 0.0f;
        if (t < 2)   g_counter[t] = 0;
    }

    // local big-count over ids [8t, 8t+8)
    int flags = 0, c = 0;
    #pragma unroll
    for (int i = 0; i < 8; i++) {
        int g  = t * 8 + i;
        int sz = ptr[g + 1] - ptr[g];
        int b  = (sz >= BIG) ? 1 : 0;
        flags |= b << i;
        c += b;
    }

    __shared__ int sc[1024];
    sc[t] = c;
    __syncthreads();
    // Hillis-Steele inclusive scan
    for (int off = 1; off < 1024; off <<= 1) {
        int v = sc[t];
        if (t >= off) v += sc[t - off];
        __syncthreads();
        sc[t] = v;
        __syncthreads();
    }
    const int B = sc[1023];                    // total big segments
    int bigpos   = sc[t] - c;                  // exclusive prefix of big
    int smallpos = B + (t * 8 - bigpos);       // stable small position

    #pragma unroll
    for (int i = 0; i < 8; i++) {
        int g = t * 8 + i;
        if ((flags >> i) & 1) ord[bigpos++]   = g;
        else                  ord[smallpos++] = g;
    }
}

// ---------------------------------------------------------------------------
// Persistent fused kernel — R11 WIN structure verbatim (164 us, DRAM 78.7%),
// queue index redirected through the stable big-first g_order.
// relu(max)==max(relu); int-bit atomicMax exact for non-negative floats.
// ptr arrays are int32 (JAX x64 disabled downcasts the int64 ptr).
// ---------------------------------------------------------------------------
__global__ void __launch_bounds__(256, 4)
seg_max_linear_kernel(const float* __restrict__ x_a,
                      const float* __restrict__ x_b,
                      const float* __restrict__ W_a,
                      const float* __restrict__ W_b,
                      const float* __restrict__ b_a,
                      const float* __restrict__ b_b,
                      const int* __restrict__ ptr_a,
                      const int* __restrict__ ptr_b,
                      float* __restrict__ out)
{
    const int ctype = blockIdx.x & 1;

    const float* x    = ctype ? x_b   : x_a;
    const int*   ptr  = ctype ? ptr_b : ptr_a;
    const float* W    = ctype ? W_b   : W_a;
    const float* bias = ctype ? b_b   : b_a;

    const int tid = threadIdx.x;               // 256
    const int c4  = tid & 15;                  // float4 column 0..15
    const int rg  = tid >> 4;                  // row group 0..15
    const int o   = tid >> 1;                  // epilogue output channel
    const int h   = tid & 1;                   // epilogue K-half

    __shared__ float4 sw[256][9];              // padded W, conflict-free
    __shared__ float4 sm[16][16];              // reduce scratch
    __shared__ float4 segv[D / 4];             // this segment's max vector
    __shared__ int    swork;

    // W -> shared once: coalesced LDG, scattered conflict-free STS.
    {
        const float4* __restrict__ W4g = reinterpret_cast<const float4*>(W);
        #pragma unroll
        for (int i = 0; i < 8; i++) {
            int f = tid + i * 256;             // float4 linear index into W
            float4 v = W4g[f];
            int row = f >> 4;                  // output row 0..127
            int kk  = f & 15;                  // float4 within row
            sw[(row << 1) | (kk >> 3)][kk & 7] = v;
        }
    }
    const float bo = bias[o];

    const float4* __restrict__ xv = reinterpret_cast<const float4*>(x);
    const float NEG = -3.402823466e38f;

    float lmax = 0.0f;                         // relu floor, running block max

    while (true) {
        if (tid == 0) swork = atomicAdd(&g_counter[ctype], 1);
        __syncthreads();                       // also covers sw visibility
        const int idx = swork;
        if (idx >= NSEG) break;
        const int g = g_order[ctype * NSEG + idx];   // big segments first

        const int gs = ptr[g];
        const int ge = ptr[g + 1];

        float4 m0 = make_float4(NEG, NEG, NEG, NEG);
        float4 m1 = m0, m2 = m0, m3 = m0;

        long long row = (long long)gs + rg;
        for (; row + 48 < ge; row += 64) {
            const float4* p = xv + row * (D / 4) + c4;
            float4 v0 = __ldcs(p);
            float4 v1 = __ldcs(p + 16 * (D / 4));
            float4 v2 = __ldcs(p + 32 * (D / 4));
            float4 v3 = __ldcs(p + 48 * (D / 4));
            fmax4(m0, v0); fmax4(m1, v1); fmax4(m2, v2); fmax4(m3, v3);
        }
        for (; row < ge; row += 16) {
            float4 v0 = __ldcs(xv + row * (D / 4) + c4);
            fmax4(m0, v0);
        }
        fmax4(m0, m1); fmax4(m2, m3); fmax4(m0, m2);

        sm[rg][c4] = m0;
        __syncthreads();

        if (tid < 16) {
            float4 m = sm[0][tid];
            #pragma unroll
            for (int j = 1; j < 16; j++)
                fmax4(m, sm[j][tid]);
            segv[tid] = m;
        }
        __syncthreads();

        // Epilogue: split-K half-dot from smem W (no register W copy).
        float a0 = 0.f, a1 = 0.f, a2 = 0.f, a3 = 0.f;
        #pragma unroll
        for (int k = 0; k < 8; k++) {
            float4 ww = sw[tid][k];            // W[o, h*32+4k .. +4)
            float4 u  = segv[h * 8 + k];
            a0 = fmaf(ww.x, u.x, a0);
            a1 = fmaf(ww.y, u.y, a1);
            a2 = fmaf(ww.z, u.z, a2);
            a3 = fmaf(ww.w, u.w, a3);
        }
        float hd    = (a0 + a1) + (a2 + a3);
        float other = __shfl_xor_sync(0xffffffffu, hd, 1);
        lmax = fmaxf(lmax, hd + other + bo);
        // next iteration's top-of-loop __syncthreads orders segv reuse
    }

    if (h == 0)
        atomicMax(reinterpret_cast<int*>(out) + o, __float_as_int(lmax));
}

// ---------------------------------------------------------------------------
extern "C" void kernel_launch(void* const* d_in, const int* in_sizes, int n_in,
                              void* d_out, int out_size)
{
    const float* x_a   = (const float*)d_in[0];
    const float* x_b   = (const float*)d_in[1];
    const float* W_a   = (const float*)d_in[2];
    const float* W_b   = (const float*)d_in[3];
    const float* b_a   = (const float*)d_in[4];
    const float* b_b   = (const float*)d_in[5];
    const int*   ptr_a = (const int*)d_in[6];
    const int*   ptr_b = (const int*)d_in[7];
    float* out = (float*)d_out;

    order_init_kernel<<<2, 1024>>>(ptr_a, ptr_b, out);
    seg_max_linear_kernel<<<NBLK, 256>>>(x_a, x_b, W_a, W_b,
                                         b_a, b_b, ptr_a, ptr_b, out);
}